// round 1
// baseline (speedup 1.0000x reference)
#include <cuda_runtime.h>
#include <math.h>

#define NN 25000
#define NE 500000
#define BQ 4
#define DD 32
#define RR 474
#define NL 4
#define KD 416          // 13*D
#define BD 128          // B*D
#define EPSF 1e-6f
#define NPB 8           // nodes per block in mlp kernel

// ---------------- scratch (no cudaMalloc allowed) ----------------
__device__ int   g_cnt[NN];
__device__ float g_deg[NN];
__device__ int   g_rowptr[NN + 1];
__device__ int   g_pos[NN];
__device__ int   g_edg[NE];
__device__ float g_scales[NN * 2];      // s1 = scale, s2 = 1/max(scale,0.01); s0==1
__device__ float g_logsum;
__device__ float g_boundary[NN * BD];
__device__ float g_hidA[NN * BD];
__device__ float g_hidB[NN * BD];
__device__ float g_relin[RR * BD];      // [r][b][d]
__device__ float g_query[BD];           // [b][d]

// ---------------- setup kernels ----------------
__global__ void zero_kernel() {
    const int stride = gridDim.x * blockDim.x;
    const int i0 = blockIdx.x * blockDim.x + threadIdx.x;
    for (int i = i0; i < NN; i += stride) { g_cnt[i] = 0; g_deg[i] = 0.0f; }
    for (int i = i0; i < NN * BD; i += stride) g_boundary[i] = 0.0f;
    if (i0 == 0) g_logsum = 0.0f;
}

__global__ void hist_kernel(const int* __restrict__ node_out,
                            const float* __restrict__ ew) {
    const int e = blockIdx.x * 256 + threadIdx.x;
    if (e < NE) {
        const int v = node_out[e];
        atomicAdd(&g_cnt[v], 1);
        atomicAdd(&g_deg[v], ew[e]);
    }
}

__global__ void scan_kernel() {
    __shared__ int sh[1024];
    __shared__ int carry;
    const int t = threadIdx.x;
    if (t == 0) carry = 0;
    __syncthreads();
    for (int base = 0; base < NN; base += 1024) {
        const int i = base + t;
        const int x = (i < NN) ? g_cnt[i] : 0;
        sh[t] = x;
        __syncthreads();
        for (int off = 1; off < 1024; off <<= 1) {
            int vv = (t >= off) ? sh[t - off] : 0;
            __syncthreads();
            sh[t] += vv;
            __syncthreads();
        }
        const int excl = carry + sh[t] - x;
        if (i < NN) { g_rowptr[i] = excl; g_pos[i] = excl; }
        __syncthreads();
        if (t == 1023) carry += sh[1023];
        __syncthreads();
    }
    if (t == 0) g_rowptr[NN] = NE;
}

__global__ void scatter_kernel(const int* __restrict__ node_out) {
    const int e = blockIdx.x * 256 + threadIdx.x;
    if (e < NE) {
        const int p = atomicAdd(&g_pos[node_out[e]], 1);
        g_edg[p] = e;
    }
}

__global__ void logsum_kernel() {
    const int i = blockIdx.x * 256 + threadIdx.x;
    float x = 0.0f;
    if (i < NN) x = logf(g_deg[i] + 1.0f);
#pragma unroll
    for (int off = 16; off > 0; off >>= 1)
        x += __shfl_down_sync(0xffffffffu, x, off);
    __shared__ float sp[8];
    if ((threadIdx.x & 31) == 0) sp[threadIdx.x >> 5] = x;
    __syncthreads();
    if (threadIdx.x == 0) {
        float s = 0.0f;
#pragma unroll
        for (int w = 0; w < 8; ++w) s += sp[w];
        atomicAdd(&g_logsum, s);
    }
}

__global__ void scales_kernel() {
    const int v = blockIdx.x * 256 + threadIdx.x;
    if (v < NN) {
        const float mean = g_logsum / (float)NN;
        const float s = logf(g_deg[v] + 1.0f) / mean;
        g_scales[v * 2 + 0] = s;
        g_scales[v * 2 + 1] = 1.0f / fmaxf(s, 0.01f);
    }
}

__global__ void init_kernel(const int* __restrict__ h_index,
                            const int* __restrict__ r_index,
                            const float* __restrict__ query_embed) {
    const int t = threadIdx.x;           // 128
    const int b = t >> 5, d = t & 31;
    const float q = query_embed[r_index[b] * DD + d];
    g_query[b * DD + d] = q;
    g_boundary[(h_index[b] * BQ + b) * DD + d] = q;
}

// rel_in[r][b][d] = sum_k query[b][k] * rel_W[l][k][r*D+d] + rel_b[l][r*D+d]
__global__ void relin_kernel(const float* __restrict__ rel_W,
                             const float* __restrict__ rel_b, int l) {
    const int t = blockIdx.x * 128 + threadIdx.x;
    if (t >= RR * BD) return;
    const int d = t & 31;
    const int b = (t >> 5) & 3;
    const int r = t >> 7;
    const float* W = rel_W + (size_t)l * DD * RR * DD + (size_t)r * DD + d;
    float acc = rel_b[(size_t)l * RR * DD + r * DD + d];
#pragma unroll
    for (int k = 0; k < DD; ++k)
        acc += g_query[b * DD + k] * W[(size_t)k * RR * DD];
    g_relin[t] = acc;   // t == (r*BQ+b)*DD + d
}

// ---------------- main conv layer: one block per node ----------------
__global__ void __launch_bounds__(128) conv_kernel(
    const int* __restrict__ node_in, const int* __restrict__ relation,
    const float* __restrict__ edge_weight,
    const float* __restrict__ lin_W, const float* __restrict__ lin_b,
    const float* __restrict__ hid_in, float* __restrict__ hid_out, int l)
{
    __shared__ float4 cat4[KD];       // [k] -> activations for b=0..3
    __shared__ float4 red4[16 * 32];  // 16 chunk partials of the 4x32 output
    __shared__ int    s_nin[128];
    __shared__ int    s_rel[128];
    __shared__ float  s_w[128];

    const int v = blockIdx.x;
    const int t = threadIdx.x;
    const int b = t >> 5, d = t & 31;

    const int start = g_rowptr[v];
    const int end   = g_rowptr[v + 1];

    // boundary self-message (weight 1) is always present
    const float m0 = g_boundary[(v * BQ + b) * DD + d];
    float sum = m0, sumsq = m0 * m0, mx = m0, mn = m0;
    const float hv = hid_in[(v * BQ + b) * DD + d];

    for (int base = start; base < end; base += 128) {
        const int n = min(128, end - base);
        __syncthreads();
        if (t < n) {
            const int e = g_edg[base + t];
            s_nin[t] = node_in[e];
            s_rel[t] = relation[e];
            s_w[t]   = edge_weight[e];
        }
        __syncthreads();
        for (int j = 0; j < n; ++j) {
            const float rv = g_relin[(s_rel[j] * BQ + b) * DD + d];
            const float hh = hid_in[(s_nin[j] * BQ + b) * DD + d];
            const float m  = rv * hh;
            const float mw = m * s_w[j];
            sum   += mw;
            sumsq += m * mw;
            mx = fmaxf(mx, mw);
            mn = fminf(mn, mw);
        }
    }

    const float cntv = (float)(g_cnt[v] + 1);
    const float inv  = 1.0f / cntv;
    const float mean = sum * inv;
    const float var  = sumsq * inv - mean * mean;
    const float sd   = sqrtf(fmaxf(var, EPSF));
    const float s1 = g_scales[v * 2 + 0];
    const float s2 = g_scales[v * 2 + 1];

    float* cat = (float*)cat4;
    cat[d * BQ + b] = hv;                       // k < 32: previous hidden
    const float stats[4] = {mean, mx, mn, sd};
#pragma unroll
    for (int st = 0; st < 4; ++st) {
        const int kb = DD + (d * 4 + st) * 3;   // update[(d*4+st)*3+sc]
        const float f = stats[st];
        cat[(kb + 0) * BQ + b] = f;             // scale 0 == 1
        cat[(kb + 1) * BQ + b] = f * s1;
        cat[(kb + 2) * BQ + b] = f * s2;
    }
    __syncthreads();

    // GEMM: out[4][32] = cat[4][416] @ W[416][32], register-blocked 4x4
    {
        const int jj = t & 7;        // j-quad: j = jj*4 + q
        const int c  = t >> 3;       // k-chunk: k in [c*26, c*26+26)
        const float* W = lin_W + (size_t)l * KD * DD + jj * 4;
        float4 a0 = {0,0,0,0}, a1 = {0,0,0,0}, a2 = {0,0,0,0}, a3 = {0,0,0,0};
        const int k0 = c * 26;
#pragma unroll
        for (int kk = 0; kk < 26; ++kk) {
            const int k = k0 + kk;
            const float4 u = cat4[k];
            const float4 w = *(const float4*)(W + (size_t)k * DD);
            a0.x += u.x * w.x; a0.y += u.x * w.y; a0.z += u.x * w.z; a0.w += u.x * w.w;
            a1.x += u.y * w.x; a1.y += u.y * w.y; a1.z += u.y * w.z; a1.w += u.y * w.w;
            a2.x += u.z * w.x; a2.y += u.z * w.y; a2.z += u.z * w.z; a2.w += u.z * w.w;
            a3.x += u.w * w.x; a3.y += u.w * w.y; a3.z += u.w * w.z; a3.w += u.w * w.w;
        }
        red4[c * 32 + 0 * 8 + jj] = a0;
        red4[c * 32 + 1 * 8 + jj] = a1;
        red4[c * 32 + 2 * 8 + jj] = a2;
        red4[c * 32 + 3 * 8 + jj] = a3;
    }
    __syncthreads();
    {
        const float* red = (const float*)red4;
        float acc = lin_b[l * DD + d];
#pragma unroll
        for (int c = 0; c < 16; ++c) acc += red[c * 128 + b * 32 + d];
        hid_out[(v * BQ + b) * DD + d] = fmaxf(acc, 0.0f);
    }
}

// ---------------- final MLP scoring ----------------
__global__ void __launch_bounds__(256) mlp_kernel(
    const float* __restrict__ hid,
    const float* __restrict__ W1, const float* __restrict__ b1,
    const float* __restrict__ W2, const float* __restrict__ b2,
    float* __restrict__ out)
{
    __shared__ float  W1s[64 * 64];
    __shared__ float  W2s[64];
    __shared__ float  b1s[64];
    __shared__ float4 f2[NPB * 64];   // [slot][k] -> 4 b's

    const int t = threadIdx.x;
    for (int i = t; i < 64 * 64; i += 256) W1s[i] = W1[i];
    if (t < 64) { W2s[t] = W2[t]; b1s[t] = b1[t]; }

    const int vbase = blockIdx.x * NPB;
    for (int i = t; i < NPB * 64 * BQ; i += 256) {
        const int bb = i & 3;
        const int k  = (i >> 2) & 63;
        const int s  = i >> 8;
        const int v  = vbase + s;
        float val = 0.0f;
        if (v < NN)
            val = (k < DD) ? hid[(v * BQ + bb) * DD + k]
                           : g_query[bb * DD + (k - DD)];
        ((float*)f2)[i] = val;
    }
    __syncthreads();

    const int s = t >> 5, lane = t & 31;
    const int v = vbase + s;
    if (v < NN) {
        float accA[4], accB[4];
#pragma unroll
        for (int bb = 0; bb < 4; ++bb) { accA[bb] = b1s[lane]; accB[bb] = b1s[lane + 32]; }
#pragma unroll 8
        for (int k = 0; k < 64; ++k) {
            const float4 u = f2[s * 64 + k];
            const float wa = W1s[k * 64 + lane];
            const float wb = W1s[k * 64 + lane + 32];
            accA[0] += u.x * wa; accA[1] += u.y * wa; accA[2] += u.z * wa; accA[3] += u.w * wa;
            accB[0] += u.x * wb; accB[1] += u.y * wb; accB[2] += u.z * wb; accB[3] += u.w * wb;
        }
        const float w2a = W2s[lane], w2b = W2s[lane + 32];
        const float bias2 = b2[0];
#pragma unroll
        for (int bb = 0; bb < 4; ++bb) {
            float p = fmaxf(accA[bb], 0.0f) * w2a + fmaxf(accB[bb], 0.0f) * w2b;
#pragma unroll
            for (int off = 16; off > 0; off >>= 1)
                p += __shfl_down_sync(0xffffffffu, p, off);
            if (lane == 0) out[bb * NN + v] = p + bias2;
        }
    }
}

// ---------------- launch ----------------
extern "C" void kernel_launch(void* const* d_in, const int* in_sizes, int n_in,
                              void* d_out, int out_size) {
    const int*   node_in     = (const int*)  d_in[0];
    const int*   node_out    = (const int*)  d_in[1];
    const int*   relation    = (const int*)  d_in[2];
    const float* edge_weight = (const float*)d_in[3];
    const int*   h_index     = (const int*)  d_in[4];
    const int*   r_index     = (const int*)  d_in[5];
    const float* query_embed = (const float*)d_in[6];
    const float* rel_W  = (const float*)d_in[7];
    const float* rel_b  = (const float*)d_in[8];
    const float* lin_W  = (const float*)d_in[9];
    const float* lin_b  = (const float*)d_in[10];
    const float* mlp_W1 = (const float*)d_in[11];
    const float* mlp_b1 = (const float*)d_in[12];
    const float* mlp_W2 = (const float*)d_in[13];
    const float* mlp_b2 = (const float*)d_in[14];
    float* out = (float*)d_out;

    float *hA, *hB, *hBound;
    cudaGetSymbolAddress((void**)&hA, g_hidA);
    cudaGetSymbolAddress((void**)&hB, g_hidB);
    cudaGetSymbolAddress((void**)&hBound, g_boundary);

    zero_kernel<<<512, 256>>>();
    hist_kernel<<<(NE + 255) / 256, 256>>>(node_out, edge_weight);
    scan_kernel<<<1, 1024>>>();
    scatter_kernel<<<(NE + 255) / 256, 256>>>(node_out);
    logsum_kernel<<<(NN + 255) / 256, 256>>>();
    scales_kernel<<<(NN + 255) / 256, 256>>>();
    init_kernel<<<1, 128>>>(h_index, r_index, query_embed);

    const float* hin = hBound;
    float* houts[4] = {hA, hB, hA, hB};
    for (int l = 0; l < NL; ++l) {
        relin_kernel<<<(RR * BD + 127) / 128, 128>>>(rel_W, rel_b, l);
        conv_kernel<<<NN, 128>>>(node_in, relation, edge_weight,
                                 lin_W, lin_b, hin, houts[l], l);
        hin = houts[l];
    }
    mlp_kernel<<<(NN + NPB - 1) / NPB, 256>>>(hin, mlp_W1, mlp_b1, mlp_W2, mlp_b2, out);
}

// round 2
// speedup vs baseline: 1.5610x; 1.5610x over previous
#include <cuda_runtime.h>
#include <math.h>

#define NN 25000
#define NE 500000
#define BQ 4
#define DD 32
#define RR 474
#define NL 4
#define KD 416          // 13*D
#define EPSF 1e-6f
#define NPB 8           // nodes per block in mlp kernel

typedef unsigned long long ull;

// ---- packed fp32x2 helpers (exact fp32, 2 MACs/instr) ----
__device__ __forceinline__ ull fma2(ull a, ull b, ull c) {
    ull d; asm("fma.rn.f32x2 %0,%1,%2,%3;" : "=l"(d) : "l"(a), "l"(b), "l"(c)); return d;
}
__device__ __forceinline__ ull add2(ull a, ull b) {
    ull d; asm("add.rn.f32x2 %0,%1,%2;" : "=l"(d) : "l"(a), "l"(b)); return d;
}
__device__ __forceinline__ ull dup2(float x) {
    ull r; asm("mov.b64 %0,{%1,%1};" : "=l"(r) : "f"(x)); return r;
}
__device__ __forceinline__ float2 unpk(ull a) {
    float2 f; asm("mov.b64 {%0,%1},%2;" : "=f"(f.x), "=f"(f.y) : "l"(a)); return f;
}

// ---------------- scratch ----------------
__device__ int    g_cnt[NN];
__device__ float  g_deg[NN];
__device__ int    g_rowptr[NN + 1];
__device__ int    g_pos[NN];
__device__ int4   g_epack[NE];          // CSR-ordered (node_in, relation, w_bits, 0)
__device__ float2 g_sc[NN];             // (s1, s2)
__device__ float  g_logsum;
__device__ float4 g_bound[NN * DD];     // [v][d] -> b-vector
__device__ float4 g_hidA[NN * DD];
__device__ float4 g_hidB[NN * DD];
__device__ float4 g_relin[RR * DD];     // [r][d] -> b-vector
__device__ float  g_query[BQ * DD];     // [b][d]
__device__ float4 g_qT[DD];             // [d] -> b-vector
__device__ float  g_csum[3 * DD];       // layer-0 std-column sums per scale

// ---------------- setup kernels ----------------
__global__ void zero_kernel() {
    const int stride = gridDim.x * blockDim.x;
    const int i0 = blockIdx.x * blockDim.x + threadIdx.x;
    for (int i = i0; i < NN; i += stride) { g_cnt[i] = 0; g_deg[i] = 0.0f; }
    float4 z = make_float4(0.f, 0.f, 0.f, 0.f);
    for (int i = i0; i < NN * DD; i += stride) g_bound[i] = z;
    if (i0 == 0) g_logsum = 0.0f;
}

__global__ void hist_kernel(const int* __restrict__ node_out,
                            const float* __restrict__ ew) {
    const int e = blockIdx.x * 256 + threadIdx.x;
    if (e < NE) {
        const int v = node_out[e];
        atomicAdd(&g_cnt[v], 1);
        atomicAdd(&g_deg[v], ew[e]);
    }
}

__global__ void scan_kernel() {
    __shared__ int sh[1024];
    __shared__ int carry;
    const int t = threadIdx.x;
    if (t == 0) carry = 0;
    __syncthreads();
    for (int base = 0; base < NN; base += 1024) {
        const int i = base + t;
        const int x = (i < NN) ? g_cnt[i] : 0;
        sh[t] = x;
        __syncthreads();
        for (int off = 1; off < 1024; off <<= 1) {
            int vv = (t >= off) ? sh[t - off] : 0;
            __syncthreads();
            sh[t] += vv;
            __syncthreads();
        }
        const int excl = carry + sh[t] - x;
        if (i < NN) { g_rowptr[i] = excl; g_pos[i] = excl; }
        __syncthreads();
        if (t == 1023) carry += sh[1023];
        __syncthreads();
    }
    if (t == 0) g_rowptr[NN] = NE;
}

__global__ void scatter_kernel(const int* __restrict__ node_in,
                               const int* __restrict__ node_out,
                               const int* __restrict__ relation,
                               const float* __restrict__ ew) {
    const int e = blockIdx.x * 256 + threadIdx.x;
    if (e < NE) {
        const int p = atomicAdd(&g_pos[node_out[e]], 1);
        g_epack[p] = make_int4(node_in[e], relation[e], __float_as_int(ew[e]), 0);
    }
}

__global__ void logsum_kernel() {
    const int i = blockIdx.x * 256 + threadIdx.x;
    float x = 0.0f;
    if (i < NN) x = logf(g_deg[i] + 1.0f);
#pragma unroll
    for (int off = 16; off > 0; off >>= 1)
        x += __shfl_down_sync(0xffffffffu, x, off);
    __shared__ float sp[8];
    if ((threadIdx.x & 31) == 0) sp[threadIdx.x >> 5] = x;
    __syncthreads();
    if (threadIdx.x == 0) {
        float s = 0.0f;
#pragma unroll
        for (int w = 0; w < 8; ++w) s += sp[w];
        atomicAdd(&g_logsum, s);
    }
}

__global__ void scales_kernel() {
    const int v = blockIdx.x * 256 + threadIdx.x;
    if (v < NN) {
        const float mean = g_logsum / (float)NN;
        const float s = logf(g_deg[v] + 1.0f) / mean;
        g_sc[v] = make_float2(s, 1.0f / fmaxf(s, 0.01f));
    }
}

__global__ void init_kernel(const int* __restrict__ h_index,
                            const int* __restrict__ r_index,
                            const float* __restrict__ query_embed) {
    const int t = threadIdx.x;           // 128
    const int b = t >> 5, d = t & 31;
    const float q = query_embed[r_index[b] * DD + d];
    g_query[b * DD + d] = q;
    ((float*)g_qT)[d * 4 + b] = q;
    ((float*)g_bound)[(h_index[b] * DD + d) * 4 + b] = q;
}

// layer-0 std-column sums: C[s][j] = sum_d W0[32 + (4d+3)*3 + s][j]
__global__ void csum_kernel(const float* __restrict__ lin_W) {
    const int j = threadIdx.x;   // 32
#pragma unroll
    for (int s = 0; s < 3; ++s) {
        float c = 0.0f;
#pragma unroll
        for (int dd = 0; dd < DD; ++dd)
            c += lin_W[(DD + (4 * dd + 3) * 3 + s) * DD + j];
        g_csum[s * DD + j] = c;
    }
}

// rel_in[r][b][d] = sum_k query[b][k] * rel_W[l][k][r*D+d] + rel_b[l][r*D+d]
__global__ void relin_kernel(const float* __restrict__ rel_W,
                             const float* __restrict__ rel_b, int l) {
    const int t = blockIdx.x * 128 + threadIdx.x;
    if (t >= RR * BQ * DD) return;
    const int d = t & 31;
    const int b = (t >> 5) & 3;
    const int r = t >> 7;
    const float* W = rel_W + (size_t)l * DD * RR * DD + (size_t)r * DD + d;
    float acc = rel_b[(size_t)l * RR * DD + r * DD + d];
#pragma unroll
    for (int k = 0; k < DD; ++k)
        acc += g_query[b * DD + k] * W[(size_t)k * RR * DD];
    ((float*)g_relin)[(r * DD + d) * 4 + b] = acc;
}

// ---------------- fused conv layer ----------------
// block = 128 threads = 4 warps = 4 nodes. Msg: warp-per-node.
// GEMM: k-split across the 4 warps, each warp covers all 4 nodes.
__device__ __forceinline__ void edge_acc(const int4 ep, const float4 rv, const float4 hh,
                                         float4& sum, float4& sq, float4& mx, float4& mn) {
    const float w = __int_as_float(ep.z);
    float m, mw;
    m = rv.x * hh.x; mw = m * w; sum.x += mw; sq.x = fmaf(m, mw, sq.x); mx.x = fmaxf(mx.x, mw); mn.x = fminf(mn.x, mw);
    m = rv.y * hh.y; mw = m * w; sum.y += mw; sq.y = fmaf(m, mw, sq.y); mx.y = fmaxf(mx.y, mw); mn.y = fminf(mn.y, mw);
    m = rv.z * hh.z; mw = m * w; sum.z += mw; sq.z = fmaf(m, mw, sq.z); mx.z = fmaxf(mx.z, mw); mn.z = fminf(mn.z, mw);
    m = rv.w * hh.w; mw = m * w; sum.w += mw; sq.w = fmaf(m, mw, sq.w); mx.w = fmaxf(mx.w, mw); mn.w = fminf(mn.w, mw);
}

__global__ void __launch_bounds__(128) conv_kernel(
    const float* __restrict__ lin_W, const float* __restrict__ lin_b,
    const float4* __restrict__ hid_in, float4* __restrict__ hid_out,
    const int* __restrict__ h_index, int layer)
{
    __shared__ float4 cat[4][KD];              // 26.6KB
    __shared__ ulonglong2 red[4][4][DD];       // [warp][slot][j], 8KB
    __shared__ int s_act[4];
    __shared__ float2 s_scl[4];

    const int t = threadIdx.x, w = t >> 5, lane = t & 31;
    const int v = blockIdx.x * 4 + w;
    const int d = lane;

    // ---- message phase (warp per node) ----
    {
        float4 m0 = g_bound[v * DD + d];
        float4 sum = m0, mx = m0, mn = m0;
        float4 sq = make_float4(m0.x * m0.x, m0.y * m0.y, m0.z * m0.z, m0.w * m0.w);
        const float4 hv = __ldg(&hid_in[v * DD + d]);
        int p = g_rowptr[v];
        const int e_ = g_rowptr[v + 1];
        int act;

        if (layer == 0) {
            const int4 h = *(const int4*)h_index;
            act = (v == h.x) | (v == h.y) | (v == h.z) | (v == h.w);
            for (; p < e_; ++p) {
                const int4 ep = __ldg(&g_epack[p]);
                const int nin = ep.x;
                if (nin == h.x || nin == h.y || nin == h.z || nin == h.w) {
                    act = 1;
                    const float4 rv = __ldg(&g_relin[ep.y * DD + d]);
                    const float4 hh = __ldg(&hid_in[nin * DD + d]);
                    edge_acc(ep, rv, hh, sum, sq, mx, mn);
                }
            }
        } else {
            act = 1;
            for (; p + 4 <= e_; p += 4) {
                const int4 e0 = __ldg(&g_epack[p + 0]);
                const int4 e1 = __ldg(&g_epack[p + 1]);
                const int4 e2 = __ldg(&g_epack[p + 2]);
                const int4 e3 = __ldg(&g_epack[p + 3]);
                const float4 rv0 = __ldg(&g_relin[e0.y * DD + d]);
                const float4 hh0 = __ldg(&hid_in[e0.x * DD + d]);
                const float4 rv1 = __ldg(&g_relin[e1.y * DD + d]);
                const float4 hh1 = __ldg(&hid_in[e1.x * DD + d]);
                const float4 rv2 = __ldg(&g_relin[e2.y * DD + d]);
                const float4 hh2 = __ldg(&hid_in[e2.x * DD + d]);
                const float4 rv3 = __ldg(&g_relin[e3.y * DD + d]);
                const float4 hh3 = __ldg(&hid_in[e3.x * DD + d]);
                edge_acc(e0, rv0, hh0, sum, sq, mx, mn);
                edge_acc(e1, rv1, hh1, sum, sq, mx, mn);
                edge_acc(e2, rv2, hh2, sum, sq, mx, mn);
                edge_acc(e3, rv3, hh3, sum, sq, mx, mn);
            }
            for (; p < e_; ++p) {
                const int4 e0 = __ldg(&g_epack[p]);
                const float4 rv0 = __ldg(&g_relin[e0.y * DD + d]);
                const float4 hh0 = __ldg(&hid_in[e0.x * DD + d]);
                edge_acc(e0, rv0, hh0, sum, sq, mx, mn);
            }
        }

        if (lane == 0) { s_act[w] = act; s_scl[w] = g_sc[v]; }

        if (act) {
            const float inv = 1.0f / (float)(g_cnt[v] + 1);
            float4 mean, var, sd;
            mean.x = sum.x * inv; mean.y = sum.y * inv; mean.z = sum.z * inv; mean.w = sum.w * inv;
            var.x = sq.x * inv - mean.x * mean.x; var.y = sq.y * inv - mean.y * mean.y;
            var.z = sq.z * inv - mean.z * mean.z; var.w = sq.w * inv - mean.w * mean.w;
            sd.x = sqrtf(fmaxf(var.x, EPSF)); sd.y = sqrtf(fmaxf(var.y, EPSF));
            sd.z = sqrtf(fmaxf(var.z, EPSF)); sd.w = sqrtf(fmaxf(var.w, EPSF));
            const float2 sc = g_sc[v];
            cat[w][d] = hv;
            const float4 st[4] = {mean, mx, mn, sd};
#pragma unroll
            for (int si = 0; si < 4; ++si) {
                const int kb = DD + (d * 4 + si) * 3;
                const float4 f = st[si];
                cat[w][kb + 0] = f;
                cat[w][kb + 1] = make_float4(f.x * sc.x, f.y * sc.x, f.z * sc.x, f.w * sc.x);
                cat[w][kb + 2] = make_float4(f.x * sc.y, f.y * sc.y, f.z * sc.y, f.w * sc.y);
            }
        }
    }
    __syncthreads();

    const int a0 = s_act[0], a1 = s_act[1], a2 = s_act[2], a3 = s_act[3];

    // ---- GEMM: warp w covers k in [w*104, w*104+104) for all 4 slots ----
    if (a0 | a1 | a2 | a3) {
        ull acc00 = 0, acc01 = 0, acc10 = 0, acc11 = 0;
        ull acc20 = 0, acc21 = 0, acc30 = 0, acc31 = 0;
        const float* W = lin_W + (size_t)layer * KD * DD;
        const ulonglong2* c0p = (const ulonglong2*)&cat[0][0];
        const ulonglong2* c1p = (const ulonglong2*)&cat[1][0];
        const ulonglong2* c2p = (const ulonglong2*)&cat[2][0];
        const ulonglong2* c3p = (const ulonglong2*)&cat[3][0];
        const int k0 = w * (KD / 4);

        if (a0 & a1 & a2 & a3) {
#pragma unroll 4
            for (int kk = 0; kk < KD / 4; ++kk) {
                const int k = k0 + kk;
                const ull w2 = dup2(__ldg(&W[k * DD + lane]));
                ulonglong2 c;
                c = c0p[k]; acc00 = fma2(c.x, w2, acc00); acc01 = fma2(c.y, w2, acc01);
                c = c1p[k]; acc10 = fma2(c.x, w2, acc10); acc11 = fma2(c.y, w2, acc11);
                c = c2p[k]; acc20 = fma2(c.x, w2, acc20); acc21 = fma2(c.y, w2, acc21);
                c = c3p[k]; acc30 = fma2(c.x, w2, acc30); acc31 = fma2(c.y, w2, acc31);
            }
        } else {
            for (int kk = 0; kk < KD / 4; ++kk) {
                const int k = k0 + kk;
                const ull w2 = dup2(__ldg(&W[k * DD + lane]));
                ulonglong2 c;
                if (a0) { c = c0p[k]; acc00 = fma2(c.x, w2, acc00); acc01 = fma2(c.y, w2, acc01); }
                if (a1) { c = c1p[k]; acc10 = fma2(c.x, w2, acc10); acc11 = fma2(c.y, w2, acc11); }
                if (a2) { c = c2p[k]; acc20 = fma2(c.x, w2, acc20); acc21 = fma2(c.y, w2, acc21); }
                if (a3) { c = c3p[k]; acc30 = fma2(c.x, w2, acc30); acc31 = fma2(c.y, w2, acc31); }
            }
        }
        red[w][0][lane] = make_ulonglong2(acc00, acc01);
        red[w][1][lane] = make_ulonglong2(acc10, acc11);
        red[w][2][lane] = make_ulonglong2(acc20, acc21);
        red[w][3][lane] = make_ulonglong2(acc30, acc31);
    }
    __syncthreads();

    // ---- epilogue: warp w finalizes node slot w ----
    {
        const float bias = lin_b[layer * DD + lane];
        float4 o;
        if (s_act[w]) {
            const ulonglong2 r0 = red[0][w][lane];
            const ulonglong2 r1 = red[1][w][lane];
            const ulonglong2 r2 = red[2][w][lane];
            const ulonglong2 r3 = red[3][w][lane];
            const ull p0 = add2(add2(r0.x, r1.x), add2(r2.x, r3.x));
            const ull p1 = add2(add2(r0.y, r1.y), add2(r2.y, r3.y));
            const float2 f0 = unpk(p0), f1 = unpk(p1);
            o = make_float4(fmaxf(f0.x + bias, 0.0f), fmaxf(f0.y + bias, 0.0f),
                            fmaxf(f1.x + bias, 0.0f), fmaxf(f1.y + bias, 0.0f));
        } else {
            // exact fast path: all messages + hidden + boundary are exactly 0
            const float sd = sqrtf(EPSF);
            const float2 sc = s_scl[w];
            const float c = g_csum[lane] + sc.x * g_csum[DD + lane] + sc.y * g_csum[2 * DD + lane];
            const float val = fmaxf(bias + sd * c, 0.0f);
            o = make_float4(val, val, val, val);
        }
        hid_out[v * DD + lane] = o;
    }
}

// ---------------- final MLP scoring ----------------
__global__ void __launch_bounds__(256) mlp_kernel(
    const float4* __restrict__ hid,
    const float* __restrict__ W1, const float* __restrict__ b1,
    const float* __restrict__ W2, const float* __restrict__ b2,
    float* __restrict__ out)
{
    __shared__ float  W1s[64 * 64];
    __shared__ float  W2s[64];
    __shared__ float  b1s[64];
    __shared__ float4 f2[NPB * 64];   // [slot][k] -> 4 b's

    const int t = threadIdx.x;
    for (int i = t; i < 64 * 64; i += 256) W1s[i] = W1[i];
    if (t < 64) { W2s[t] = W2[t]; b1s[t] = b1[t]; }

    const int vbase = blockIdx.x * NPB;
    for (int i = t; i < NPB * 64; i += 256) {
        const int k = i & 63;
        const int s = i >> 6;
        const int v = vbase + s;
        float4 val = make_float4(0.f, 0.f, 0.f, 0.f);
        if (v < NN) val = (k < DD) ? __ldg(&hid[v * DD + k]) : g_qT[k - DD];
        f2[i] = val;
    }
    __syncthreads();

    const int s = t >> 5, lane = t & 31;
    const int v = vbase + s;
    if (v < NN) {
        float accA[4], accB[4];
#pragma unroll
        for (int bb = 0; bb < 4; ++bb) { accA[bb] = b1s[lane]; accB[bb] = b1s[lane + 32]; }
#pragma unroll 8
        for (int k = 0; k < 64; ++k) {
            const float4 u = f2[s * 64 + k];
            const float wa = W1s[k * 64 + lane];
            const float wb = W1s[k * 64 + lane + 32];
            accA[0] += u.x * wa; accA[1] += u.y * wa; accA[2] += u.z * wa; accA[3] += u.w * wa;
            accB[0] += u.x * wb; accB[1] += u.y * wb; accB[2] += u.z * wb; accB[3] += u.w * wb;
        }
        const float w2a = W2s[lane], w2b = W2s[lane + 32];
        const float bias2 = b2[0];
#pragma unroll
        for (int bb = 0; bb < 4; ++bb) {
            float p = fmaxf(accA[bb], 0.0f) * w2a + fmaxf(accB[bb], 0.0f) * w2b;
#pragma unroll
            for (int off = 16; off > 0; off >>= 1)
                p += __shfl_down_sync(0xffffffffu, p, off);
            if (lane == 0) out[bb * NN + v] = p + bias2;
        }
    }
}

// ---------------- launch ----------------
extern "C" void kernel_launch(void* const* d_in, const int* in_sizes, int n_in,
                              void* d_out, int out_size) {
    const int*   node_in     = (const int*)  d_in[0];
    const int*   node_out    = (const int*)  d_in[1];
    const int*   relation    = (const int*)  d_in[2];
    const float* edge_weight = (const float*)d_in[3];
    const int*   h_index     = (const int*)  d_in[4];
    const int*   r_index     = (const int*)  d_in[5];
    const float* query_embed = (const float*)d_in[6];
    const float* rel_W  = (const float*)d_in[7];
    const float* rel_b  = (const float*)d_in[8];
    const float* lin_W  = (const float*)d_in[9];
    const float* lin_b  = (const float*)d_in[10];
    const float* mlp_W1 = (const float*)d_in[11];
    const float* mlp_b1 = (const float*)d_in[12];
    const float* mlp_W2 = (const float*)d_in[13];
    const float* mlp_b2 = (const float*)d_in[14];
    float* out = (float*)d_out;

    float4 *hA, *hB, *hBound;
    cudaGetSymbolAddress((void**)&hA, g_hidA);
    cudaGetSymbolAddress((void**)&hB, g_hidB);
    cudaGetSymbolAddress((void**)&hBound, g_bound);

    zero_kernel<<<512, 256>>>();
    hist_kernel<<<(NE + 255) / 256, 256>>>(node_out, edge_weight);
    scan_kernel<<<1, 1024>>>();
    scatter_kernel<<<(NE + 255) / 256, 256>>>(node_in, node_out, relation, edge_weight);
    logsum_kernel<<<(NN + 255) / 256, 256>>>();
    scales_kernel<<<(NN + 255) / 256, 256>>>();
    init_kernel<<<1, 128>>>(h_index, r_index, query_embed);
    csum_kernel<<<1, 32>>>(lin_W);

    const float4* hin = hBound;
    float4* houts[4] = {hA, hB, hA, hB};
    for (int l = 0; l < NL; ++l) {
        relin_kernel<<<(RR * BQ * DD + 127) / 128, 128>>>(rel_W, rel_b, l);
        conv_kernel<<<NN / 4, 128>>>(lin_W, lin_b, hin, houts[l], h_index, l);
        hin = houts[l];
    }
    mlp_kernel<<<(NN + NPB - 1) / NPB, 256>>>(hin, mlp_W1, mlp_b1, mlp_W2, mlp_b2, out);
}

// round 3
// speedup vs baseline: 1.5815x; 1.0131x over previous
#include <cuda_runtime.h>
#include <math.h>

#define NN 25000
#define NE 500000
#define BQ 4
#define DD 32
#define RR 474
#define NL 4
#define KD 416          // 13*D
#define KH 208          // KD/2
#define EPSF 1e-6f
#define NPB 8
#define SCAN_B 25       // ceil(25000/1024)

typedef unsigned long long ull;

// ---- packed fp32x2 helpers (exact fp32, 2 MACs/instr) ----
__device__ __forceinline__ ull fma2(ull a, ull b, ull c) {
    ull d; asm("fma.rn.f32x2 %0,%1,%2,%3;" : "=l"(d) : "l"(a), "l"(b), "l"(c)); return d;
}
__device__ __forceinline__ ull add2(ull a, ull b) {
    ull d; asm("add.rn.f32x2 %0,%1,%2;" : "=l"(d) : "l"(a), "l"(b)); return d;
}
__device__ __forceinline__ ull dup2(float x) {
    ull r; asm("mov.b64 %0,{%1,%1};" : "=l"(r) : "f"(x)); return r;
}
__device__ __forceinline__ float2 unpk(ull a) {
    float2 f; asm("mov.b64 {%0,%1},%2;" : "=f"(f.x), "=f"(f.y) : "l"(a)); return f;
}

// ---------------- scratch ----------------
__device__ int    g_cnt[NN];
__device__ float  g_deg[NN];
__device__ int    g_rowptr[NN + 1];
__device__ int    g_pos[NN];
__device__ int4   g_epack[NE];          // CSR-ordered (node_in, relation, w_bits, 0)
__device__ float2 g_sc[NN];             // (s1, s2)
__device__ int    g_bsum[SCAN_B];
__device__ float  g_logpart[SCAN_B];
__device__ float4 g_bound[NN * DD];     // [v][d] -> b-vector
__device__ float4 g_hidA[NN * DD];
__device__ float4 g_hidB[NN * DD];
__device__ float4 g_relin[NL * RR * DD]; // [l][r][d] -> b-vector
__device__ float  g_query[BQ * DD];     // [b][d]
__device__ float4 g_qT[DD];             // [d] -> b-vector
__device__ float  g_csum[3 * DD];       // layer-0 std-column sums per scale

// ---------------- setup kernels ----------------
__global__ void zero_kernel() {
    const int stride = gridDim.x * blockDim.x;
    const int i0 = blockIdx.x * blockDim.x + threadIdx.x;
    for (int i = i0; i < NN; i += stride) { g_cnt[i] = 0; g_deg[i] = 0.0f; }
    float4 z = make_float4(0.f, 0.f, 0.f, 0.f);
    for (int i = i0; i < NN * DD; i += stride) g_bound[i] = z;
}

__global__ void hist_kernel(const int* __restrict__ node_out,
                            const float* __restrict__ ew) {
    const int e = blockIdx.x * 256 + threadIdx.x;
    if (e < NE) {
        const int v = node_out[e];
        atomicAdd(&g_cnt[v], 1);
        atomicAdd(&g_deg[v], ew[e]);
    }
}

// block-local exclusive scan of g_cnt + block totals + log-degree partial sums
__global__ void __launch_bounds__(1024) scanA_kernel() {
    __shared__ int wsum[32];
    __shared__ int woff[32];
    __shared__ float lsum[32];
    const int t = threadIdx.x, wid = t >> 5, lane = t & 31;
    const int i = blockIdx.x * 1024 + t;
    const int x = (i < NN) ? g_cnt[i] : 0;
    float y = (i < NN) ? logf(g_deg[i] + 1.0f) : 0.0f;

    int incl = x;
#pragma unroll
    for (int off = 1; off < 32; off <<= 1) {
        int n = __shfl_up_sync(0xffffffffu, incl, off);
        if (lane >= off) incl += n;
    }
#pragma unroll
    for (int off = 16; off > 0; off >>= 1)
        y += __shfl_down_sync(0xffffffffu, y, off);
    if (lane == 31) wsum[wid] = incl;
    if (lane == 0)  lsum[wid] = y;
    __syncthreads();
    if (wid == 0) {
        int s = wsum[lane];
        int si = s;
#pragma unroll
        for (int off = 1; off < 32; off <<= 1) {
            int n = __shfl_up_sync(0xffffffffu, si, off);
            if (lane >= off) si += n;
        }
        woff[lane] = si - s;   // exclusive warp offset
        float ls = lsum[lane];
#pragma unroll
        for (int off = 16; off > 0; off >>= 1)
            ls += __shfl_down_sync(0xffffffffu, ls, off);
        if (lane == 31) g_bsum[blockIdx.x] = si;  // block total
        if (lane == 0)  g_logpart[blockIdx.x] = ls;
    }
    __syncthreads();
    if (i < NN) g_rowptr[i] = incl - x + woff[wid];   // block-local exclusive
}

// add global offsets, init g_pos, compute scales
__global__ void __launch_bounds__(1024) scanB_kernel() {
    const int t = threadIdx.x;
    const int i = blockIdx.x * 1024 + t;
    int off = 0;
    float gl = 0.0f;
#pragma unroll
    for (int j = 0; j < SCAN_B; ++j) {
        if (j < blockIdx.x) off += g_bsum[j];
        gl += g_logpart[j];
    }
    if (i < NN) {
        const int rp = g_rowptr[i] + off;
        g_rowptr[i] = rp;
        g_pos[i] = rp;
        const float mean = gl / (float)NN;
        const float s = logf(g_deg[i] + 1.0f) / mean;
        g_sc[i] = make_float2(s, 1.0f / fmaxf(s, 0.01f));
    }
    if (i == 0) g_rowptr[NN] = NE;
}

__global__ void scatter_kernel(const int* __restrict__ node_in,
                               const int* __restrict__ node_out,
                               const int* __restrict__ relation,
                               const float* __restrict__ ew) {
    const int e = blockIdx.x * 256 + threadIdx.x;
    if (e < NE) {
        const int p = atomicAdd(&g_pos[node_out[e]], 1);
        g_epack[p] = make_int4(node_in[e], relation[e], __float_as_int(ew[e]), 0);
    }
}

// init (warps 0-3) + layer-0 std-column sums (warp 4)
__global__ void init_kernel(const int* __restrict__ h_index,
                            const int* __restrict__ r_index,
                            const float* __restrict__ query_embed,
                            const float* __restrict__ lin_W) {
    const int t = threadIdx.x;           // 160
    if (t < 128) {
        const int b = t >> 5, d = t & 31;
        const float q = query_embed[r_index[b] * DD + d];
        g_query[b * DD + d] = q;
        ((float*)g_qT)[d * 4 + b] = q;
        ((float*)g_bound)[(h_index[b] * DD + d) * 4 + b] = q;
    } else {
        const int j = t - 128;           // 32
#pragma unroll
        for (int s = 0; s < 3; ++s) {
            float c = 0.0f;
#pragma unroll
            for (int dd = 0; dd < DD; ++dd)
                c += lin_W[(DD + (4 * dd + 3) * 3 + s) * DD + j];
            g_csum[s * DD + j] = c;
        }
    }
}

// all layers' rel_in in one launch: grid = NL*RR blocks of 128
__global__ void relin_kernel(const float* __restrict__ rel_W,
                             const float* __restrict__ rel_b) {
    const int bx = blockIdx.x;
    const int l = bx / RR, r = bx - l * RR;
    const int t = threadIdx.x;
    const int d = t & 31, b = t >> 5;
    const float* W = rel_W + (size_t)l * DD * RR * DD + (size_t)r * DD + d;
    float acc = rel_b[(size_t)l * RR * DD + r * DD + d];
#pragma unroll
    for (int k = 0; k < DD; ++k)
        acc += g_query[b * DD + k] * W[(size_t)k * RR * DD];
    ((float*)g_relin)[((size_t)(l * RR + r) * DD + d) * 4 + b] = acc;
}

// ---------------- fused conv layer ----------------
__device__ __forceinline__ void edge_acc(const int4 ep, const float4 rv, const float4 hh,
                                         float4& sum, float4& sq, float4& mx, float4& mn) {
    const float w = __int_as_float(ep.z);
    float m, mw;
    m = rv.x * hh.x; mw = m * w; sum.x += mw; sq.x = fmaf(m, mw, sq.x); mx.x = fmaxf(mx.x, mw); mn.x = fminf(mn.x, mw);
    m = rv.y * hh.y; mw = m * w; sum.y += mw; sq.y = fmaf(m, mw, sq.y); mx.y = fmaxf(mx.y, mw); mn.y = fminf(mn.y, mw);
    m = rv.z * hh.z; mw = m * w; sum.z += mw; sq.z = fmaf(m, mw, sq.z); mx.z = fmaxf(mx.z, mw); mn.z = fminf(mn.z, mw);
    m = rv.w * hh.w; mw = m * w; sum.w += mw; sq.w = fmaf(m, mw, sq.w); mx.w = fmaxf(mx.w, mw); mn.w = fminf(mn.w, mw);
}

__global__ void __launch_bounds__(128) conv_kernel(
    const float* __restrict__ lin_W, const float* __restrict__ lin_b,
    const float4* __restrict__ hid_in, float4* __restrict__ hid_out,
    const int* __restrict__ h_index, int layer)
{
    __shared__ float4 cat[4][KD];              // 26.6KB
    __shared__ ulonglong2 red[2][4][DD];       // [khalf][slot][j], 4KB
    __shared__ int s_act[4];
    __shared__ float2 s_scl[4];

    const int t = threadIdx.x, w = t >> 5, lane = t & 31;
    const int v = blockIdx.x * 4 + w;
    const int d = lane;
    const float4* relin = g_relin + (size_t)layer * RR * DD;

    // ---- message phase (warp per node) ----
    {
        float4 m0 = g_bound[v * DD + d];
        float4 sum = m0, mx = m0, mn = m0;
        float4 sq = make_float4(m0.x * m0.x, m0.y * m0.y, m0.z * m0.z, m0.w * m0.w);
        const float4 hv = __ldg(&hid_in[v * DD + d]);
        int p = g_rowptr[v];
        const int e_ = g_rowptr[v + 1];
        const int degv = e_ - p;
        int act;

        if (layer == 0) {
            const int4 h = *(const int4*)h_index;
            act = (v == h.x) | (v == h.y) | (v == h.z) | (v == h.w);
            int nacc = 0;
            for (; p < e_; ++p) {
                const int4 ep = __ldg(&g_epack[p]);
                const int nin = ep.x;
                if (nin == h.x || nin == h.y || nin == h.z || nin == h.w) {
                    act = 1; ++nacc;
                    const float4 rv = __ldg(&relin[ep.y * DD + d]);
                    const float4 hh = __ldg(&hid_in[nin * DD + d]);
                    edge_acc(ep, rv, hh, sum, sq, mx, mn);
                }
            }
            if (nacc < degv) {
                // zero messages from inactive sources participate in max/min
                mx.x = fmaxf(mx.x, 0.f); mx.y = fmaxf(mx.y, 0.f); mx.z = fmaxf(mx.z, 0.f); mx.w = fmaxf(mx.w, 0.f);
                mn.x = fminf(mn.x, 0.f); mn.y = fminf(mn.y, 0.f); mn.z = fminf(mn.z, 0.f); mn.w = fminf(mn.w, 0.f);
            }
        } else {
            act = 1;
            for (; p + 4 <= e_; p += 4) {
                const int4 e0 = __ldg(&g_epack[p + 0]);
                const int4 e1 = __ldg(&g_epack[p + 1]);
                const int4 e2 = __ldg(&g_epack[p + 2]);
                const int4 e3 = __ldg(&g_epack[p + 3]);
                const float4 rv0 = __ldg(&relin[e0.y * DD + d]);
                const float4 hh0 = __ldg(&hid_in[e0.x * DD + d]);
                const float4 rv1 = __ldg(&relin[e1.y * DD + d]);
                const float4 hh1 = __ldg(&hid_in[e1.x * DD + d]);
                const float4 rv2 = __ldg(&relin[e2.y * DD + d]);
                const float4 hh2 = __ldg(&hid_in[e2.x * DD + d]);
                const float4 rv3 = __ldg(&relin[e3.y * DD + d]);
                const float4 hh3 = __ldg(&hid_in[e3.x * DD + d]);
                edge_acc(e0, rv0, hh0, sum, sq, mx, mn);
                edge_acc(e1, rv1, hh1, sum, sq, mx, mn);
                edge_acc(e2, rv2, hh2, sum, sq, mx, mn);
                edge_acc(e3, rv3, hh3, sum, sq, mx, mn);
            }
            for (; p < e_; ++p) {
                const int4 e0 = __ldg(&g_epack[p]);
                const float4 rv0 = __ldg(&relin[e0.y * DD + d]);
                const float4 hh0 = __ldg(&hid_in[e0.x * DD + d]);
                edge_acc(e0, rv0, hh0, sum, sq, mx, mn);
            }
        }

        if (lane == 0) { s_act[w] = act; s_scl[w] = g_sc[v]; }

        if (act) {
            const float inv = 1.0f / (float)(degv + 1);
            float4 mean, var, sd;
            mean.x = sum.x * inv; mean.y = sum.y * inv; mean.z = sum.z * inv; mean.w = sum.w * inv;
            var.x = sq.x * inv - mean.x * mean.x; var.y = sq.y * inv - mean.y * mean.y;
            var.z = sq.z * inv - mean.z * mean.z; var.w = sq.w * inv - mean.w * mean.w;
            sd.x = sqrtf(fmaxf(var.x, EPSF)); sd.y = sqrtf(fmaxf(var.y, EPSF));
            sd.z = sqrtf(fmaxf(var.z, EPSF)); sd.w = sqrtf(fmaxf(var.w, EPSF));
            const float2 sc = g_sc[v];
            cat[w][d] = hv;
            const float4 st[4] = {mean, mx, mn, sd};
#pragma unroll
            for (int si = 0; si < 4; ++si) {
                const int kb = DD + (d * 4 + si) * 3;
                const float4 f = st[si];
                cat[w][kb + 0] = f;
                cat[w][kb + 1] = make_float4(f.x * sc.x, f.y * sc.x, f.z * sc.x, f.w * sc.x);
                cat[w][kb + 2] = make_float4(f.x * sc.y, f.y * sc.y, f.z * sc.y, f.w * sc.y);
            }
        }
    }
    __syncthreads();

    const int anyact = s_act[0] | s_act[1] | s_act[2] | s_act[3];

    // ---- GEMM: warp = (node-pair, k-half); lane = output column j ----
    // cat reads are broadcast LDS (1 crossbar phase), W reads are coalesced
    // LDG.32 (L1-resident since shared by all blocks).
    if (anyact) {
        const int pair = w & 1;         // nodes 2*pair, 2*pair+1
        const int kh = w >> 1;          // k in [kh*208, kh*208+208)
        const ulonglong2* cA = (const ulonglong2*)&cat[2 * pair][0]     + kh * KH;
        const ulonglong2* cB = (const ulonglong2*)&cat[2 * pair + 1][0] + kh * KH;
        const float* Wp = lin_W + (size_t)layer * KD * DD + (size_t)kh * KH * DD + lane;
        ull aA0 = 0, aA1 = 0, aB0 = 0, aB1 = 0;
#pragma unroll 4
        for (int kk = 0; kk < KH; ++kk) {
            const ull w2 = dup2(__ldg(&Wp[kk * DD]));
            const ulonglong2 c0 = cA[kk];
            const ulonglong2 c1 = cB[kk];
            aA0 = fma2(c0.x, w2, aA0); aA1 = fma2(c0.y, w2, aA1);
            aB0 = fma2(c1.x, w2, aB0); aB1 = fma2(c1.y, w2, aB1);
        }
        red[kh][2 * pair][lane]     = make_ulonglong2(aA0, aA1);
        red[kh][2 * pair + 1][lane] = make_ulonglong2(aB0, aB1);
    }
    __syncthreads();

    // ---- epilogue: warp w finalizes node slot w ----
    {
        const float bias = lin_b[layer * DD + lane];
        float4 o;
        if (s_act[w]) {
            const ulonglong2 r0 = red[0][w][lane];
            const ulonglong2 r1 = red[1][w][lane];
            const ull p0 = add2(r0.x, r1.x);
            const ull p1 = add2(r0.y, r1.y);
            const float2 f0 = unpk(p0), f1 = unpk(p1);
            o = make_float4(fmaxf(f0.x + bias, 0.0f), fmaxf(f0.y + bias, 0.0f),
                            fmaxf(f1.x + bias, 0.0f), fmaxf(f1.y + bias, 0.0f));
        } else {
            // exact fast path: all messages + hidden + boundary exactly 0
            const float sd = sqrtf(EPSF);
            const float2 sc = s_scl[w];
            const float c = g_csum[lane] + sc.x * g_csum[DD + lane] + sc.y * g_csum[2 * DD + lane];
            const float val = fmaxf(bias + sd * c, 0.0f);
            o = make_float4(val, val, val, val);
        }
        hid_out[v * DD + lane] = o;
    }
}

// ---------------- final MLP scoring ----------------
__global__ void __launch_bounds__(256) mlp_kernel(
    const float4* __restrict__ hid,
    const float* __restrict__ W1, const float* __restrict__ b1,
    const float* __restrict__ W2, const float* __restrict__ b2,
    float* __restrict__ out)
{
    __shared__ float  W1s[64 * 64];
    __shared__ float  W2s[64];
    __shared__ float  b1s[64];
    __shared__ float4 f2[NPB * 64];   // [slot][k] -> 4 b's

    const int t = threadIdx.x;
    for (int i = t; i < 64 * 64; i += 256) W1s[i] = W1[i];
    if (t < 64) { W2s[t] = W2[t]; b1s[t] = b1[t]; }

    const int vbase = blockIdx.x * NPB;
    for (int i = t; i < NPB * 64; i += 256) {
        const int k = i & 63;
        const int s = i >> 6;
        const int v = vbase + s;
        float4 val = make_float4(0.f, 0.f, 0.f, 0.f);
        if (v < NN) val = (k < DD) ? __ldg(&hid[v * DD + k]) : g_qT[k - DD];
        f2[i] = val;
    }
    __syncthreads();

    const int s = t >> 5, lane = t & 31;
    const int v = vbase + s;
    if (v < NN) {
        float accA[4], accB[4];
#pragma unroll
        for (int bb = 0; bb < 4; ++bb) { accA[bb] = b1s[lane]; accB[bb] = b1s[lane + 32]; }
#pragma unroll 8
        for (int k = 0; k < 64; ++k) {
            const float4 u = f2[s * 64 + k];
            const float wa = W1s[k * 64 + lane];
            const float wb = W1s[k * 64 + lane + 32];
            accA[0] += u.x * wa; accA[1] += u.y * wa; accA[2] += u.z * wa; accA[3] += u.w * wa;
            accB[0] += u.x * wb; accB[1] += u.y * wb; accB[2] += u.z * wb; accB[3] += u.w * wb;
        }
        const float w2a = W2s[lane], w2b = W2s[lane + 32];
        const float bias2 = b2[0];
#pragma unroll
        for (int bb = 0; bb < 4; ++bb) {
            float p = fmaxf(accA[bb], 0.0f) * w2a + fmaxf(accB[bb], 0.0f) * w2b;
#pragma unroll
            for (int off = 16; off > 0; off >>= 1)
                p += __shfl_down_sync(0xffffffffu, p, off);
            if (lane == 0) out[bb * NN + v] = p + bias2;
        }
    }
}

// ---------------- launch ----------------
extern "C" void kernel_launch(void* const* d_in, const int* in_sizes, int n_in,
                              void* d_out, int out_size) {
    const int*   node_in     = (const int*)  d_in[0];
    const int*   node_out    = (const int*)  d_in[1];
    const int*   relation    = (const int*)  d_in[2];
    const float* edge_weight = (const float*)d_in[3];
    const int*   h_index     = (const int*)  d_in[4];
    const int*   r_index     = (const int*)  d_in[5];
    const float* query_embed = (const float*)d_in[6];
    const float* rel_W  = (const float*)d_in[7];
    const float* rel_b  = (const float*)d_in[8];
    const float* lin_W  = (const float*)d_in[9];
    const float* lin_b  = (const float*)d_in[10];
    const float* mlp_W1 = (const float*)d_in[11];
    const float* mlp_b1 = (const float*)d_in[12];
    const float* mlp_W2 = (const float*)d_in[13];
    const float* mlp_b2 = (const float*)d_in[14];
    float* out = (float*)d_out;

    float4 *hA, *hB, *hBound;
    cudaGetSymbolAddress((void**)&hA, g_hidA);
    cudaGetSymbolAddress((void**)&hB, g_hidB);
    cudaGetSymbolAddress((void**)&hBound, g_bound);

    zero_kernel<<<512, 256>>>();
    hist_kernel<<<(NE + 255) / 256, 256>>>(node_out, edge_weight);
    scanA_kernel<<<SCAN_B, 1024>>>();
    scanB_kernel<<<SCAN_B, 1024>>>();
    scatter_kernel<<<(NE + 255) / 256, 256>>>(node_in, node_out, relation, edge_weight);
    init_kernel<<<1, 160>>>(h_index, r_index, query_embed, lin_W);
    relin_kernel<<<NL * RR, 128>>>(rel_W, rel_b);

    const float4* hin = hBound;
    float4* houts[4] = {hA, hB, hA, hB};
    for (int l = 0; l < NL; ++l) {
        conv_kernel<<<NN / 4, 128>>>(lin_W, lin_b, hin, houts[l], h_index, l);
        hin = houts[l];
    }
    mlp_kernel<<<(NN + NPB - 1) / NPB, 256>>>(hin, mlp_W1, mlp_b1, mlp_W2, mlp_b2, out);
}

// round 4
// speedup vs baseline: 2.2767x; 1.4396x over previous
#include <cuda_runtime.h>
#include <math.h>
#include <stdint.h>

#define NN 25000
#define NE 500000
#define BQ 4
#define DD 32
#define RR 474
#define NL 4
#define KD 416          // 13*D
#define NSTEP 26        // KD/16 k-steps
#define EPSF 1e-6f
#define NPB 8
#define SCAN_B 25       // ceil(25000/1024)

typedef unsigned long long ull;

// ---- packed fp32x2 helpers (exact fp32, 2 MACs/instr) ----
__device__ __forceinline__ ull fma2(ull a, ull b, ull c) {
    ull d; asm("fma.rn.f32x2 %0,%1,%2,%3;" : "=l"(d) : "l"(a), "l"(b), "l"(c)); return d;
}
__device__ __forceinline__ ull dup2(float x) {
    ull r; asm("mov.b64 %0,{%1,%1};" : "=l"(r) : "f"(x)); return r;
}
__device__ __forceinline__ float2 unpk(ull a) {
    float2 f; asm("mov.b64 {%0,%1},%2;" : "=f"(f.x), "=f"(f.y) : "l"(a)); return f;
}

// split (x0,x1) into bf16 hi pair + bf16 lo pair (lo = x - float(hi))
__device__ __forceinline__ void split2(float x0, float x1, uint32_t& h, uint32_t& l) {
    uint32_t hp; asm("cvt.rn.bf16x2.f32 %0,%1,%2;" : "=r"(hp) : "f"(x1), "f"(x0));
    const float l0 = x0 - __int_as_float(hp << 16);
    const float l1 = x1 - __int_as_float(hp & 0xFFFF0000u);
    uint32_t lp; asm("cvt.rn.bf16x2.f32 %0,%1,%2;" : "=r"(lp) : "f"(l1), "f"(l0));
    h = hp; l = lp;
}

__device__ __forceinline__ void mma16816(float& d0, float& d1, float& d2, float& d3,
                                         uint32_t a0, uint32_t a1, uint32_t a2, uint32_t a3,
                                         uint32_t b0, uint32_t b1) {
    asm volatile("mma.sync.aligned.m16n8k16.row.col.f32.bf16.bf16.f32 "
                 "{%0,%1,%2,%3},{%4,%5,%6,%7},{%8,%9},{%0,%1,%2,%3};"
                 : "+f"(d0), "+f"(d1), "+f"(d2), "+f"(d3)
                 : "r"(a0), "r"(a1), "r"(a2), "r"(a3), "r"(b0), "r"(b1));
}

// ---------------- scratch ----------------
__device__ int    g_cnt[NN];
__device__ float  g_deg[NN];
__device__ int    g_rowptr[NN + 1];
__device__ int    g_pos[NN];
__device__ int4   g_epack[NE];          // CSR-ordered (node_in, relation, w_bits, 0)
__device__ float2 g_sc[NN];             // (s1, s2)
__device__ int    g_bsum[SCAN_B];
__device__ float  g_logpart[SCAN_B];
__device__ float4 g_bound[NN * DD];     // [v][d] -> b-vector
__device__ float4 g_hidA[NN * DD];
__device__ float4 g_hidB[NN * DD];
__device__ float4 g_relin[NL * RR * DD]; // [l][r][d] -> b-vector
__device__ float  g_query[BQ * DD];     // [b][d]
__device__ float4 g_qT[DD];             // [d] -> b-vector
__device__ float  g_csum[3 * DD];       // layer-0 std-column sums per scale
__device__ uint4  g_Wmma[NL * NSTEP * 128]; // fragment-ordered split weights

// ---------------- setup kernels ----------------
__global__ void zero_kernel() {
    const int stride = gridDim.x * blockDim.x;
    const int i0 = blockIdx.x * blockDim.x + threadIdx.x;
    for (int i = i0; i < NN; i += stride) { g_cnt[i] = 0; g_deg[i] = 0.0f; }
    float4 z = make_float4(0.f, 0.f, 0.f, 0.f);
    for (int i = i0; i < NN * DD; i += stride) g_bound[i] = z;
}

__global__ void hist_kernel(const int* __restrict__ node_out,
                            const float* __restrict__ ew) {
    const int e = blockIdx.x * 256 + threadIdx.x;
    if (e < NE) {
        const int v = node_out[e];
        atomicAdd(&g_cnt[v], 1);
        atomicAdd(&g_deg[v], ew[e]);
    }
}

__global__ void __launch_bounds__(1024) scanA_kernel() {
    __shared__ int wsum[32];
    __shared__ int woff[32];
    __shared__ float lsum[32];
    const int t = threadIdx.x, wid = t >> 5, lane = t & 31;
    const int i = blockIdx.x * 1024 + t;
    const int x = (i < NN) ? g_cnt[i] : 0;
    float y = (i < NN) ? logf(g_deg[i] + 1.0f) : 0.0f;

    int incl = x;
#pragma unroll
    for (int off = 1; off < 32; off <<= 1) {
        int n = __shfl_up_sync(0xffffffffu, incl, off);
        if (lane >= off) incl += n;
    }
#pragma unroll
    for (int off = 16; off > 0; off >>= 1)
        y += __shfl_down_sync(0xffffffffu, y, off);
    if (lane == 31) wsum[wid] = incl;
    if (lane == 0)  lsum[wid] = y;
    __syncthreads();
    if (wid == 0) {
        int s = wsum[lane];
        int si = s;
#pragma unroll
        for (int off = 1; off < 32; off <<= 1) {
            int n = __shfl_up_sync(0xffffffffu, si, off);
            if (lane >= off) si += n;
        }
        woff[lane] = si - s;
        float ls = lsum[lane];
#pragma unroll
        for (int off = 16; off > 0; off >>= 1)
            ls += __shfl_down_sync(0xffffffffu, ls, off);
        if (lane == 31) g_bsum[blockIdx.x] = si;
        if (lane == 0)  g_logpart[blockIdx.x] = ls;
    }
    __syncthreads();
    if (i < NN) g_rowptr[i] = incl - x + woff[wid];
}

__global__ void __launch_bounds__(1024) scanB_kernel() {
    const int t = threadIdx.x;
    const int i = blockIdx.x * 1024 + t;
    int off = 0;
    float gl = 0.0f;
#pragma unroll
    for (int j = 0; j < SCAN_B; ++j) {
        if (j < blockIdx.x) off += g_bsum[j];
        gl += g_logpart[j];
    }
    if (i < NN) {
        const int rp = g_rowptr[i] + off;
        g_rowptr[i] = rp;
        g_pos[i] = rp;
        const float mean = gl / (float)NN;
        const float s = logf(g_deg[i] + 1.0f) / mean;
        g_sc[i] = make_float2(s, 1.0f / fmaxf(s, 0.01f));
    }
    if (i == 0) g_rowptr[NN] = NE;
}

__global__ void scatter_kernel(const int* __restrict__ node_in,
                               const int* __restrict__ node_out,
                               const int* __restrict__ relation,
                               const float* __restrict__ ew) {
    const int e = blockIdx.x * 256 + threadIdx.x;
    if (e < NE) {
        const int p = atomicAdd(&g_pos[node_out[e]], 1);
        g_epack[p] = make_int4(node_in[e], relation[e], __float_as_int(ew[e]), 0);
    }
}

__global__ void init_kernel(const int* __restrict__ h_index,
                            const int* __restrict__ r_index,
                            const float* __restrict__ query_embed,
                            const float* __restrict__ lin_W) {
    const int t = threadIdx.x;           // 160
    if (t < 128) {
        const int b = t >> 5, d = t & 31;
        const float q = query_embed[r_index[b] * DD + d];
        g_query[b * DD + d] = q;
        ((float*)g_qT)[d * 4 + b] = q;
        ((float*)g_bound)[(h_index[b] * DD + d) * 4 + b] = q;
    } else {
        const int j = t - 128;           // 32
#pragma unroll
        for (int s = 0; s < 3; ++s) {
            float c = 0.0f;
#pragma unroll
            for (int dd = 0; dd < DD; ++dd)
                c += lin_W[(DD + (4 * dd + 3) * 3 + s) * DD + j];
            g_csum[s * DD + j] = c;
        }
    }
}

// split lin_W into fragment-ordered bf16 hi/lo table
// layout: g_Wmma[(l*NSTEP+s)*128 + w*32+lane] = {b0_hi, b1_hi, b0_lo, b1_lo}
__global__ void wsplit_kernel(const float* __restrict__ lin_W) {
    const int l = blockIdx.x / NSTEP, s = blockIdx.x % NSTEP;
    const int t = threadIdx.x;
    const int w = t >> 5, lane = t & 31;
    const int c = lane & 3, n = 8 * w + (lane >> 2);
    const int k0 = 16 * s;
    const float* W = lin_W + (size_t)l * KD * DD;
    const float w00 = W[(k0 + 2 * c) * DD + n];
    const float w01 = W[(k0 + 2 * c + 1) * DD + n];
    const float w10 = W[(k0 + 8 + 2 * c) * DD + n];
    const float w11 = W[(k0 + 9 + 2 * c) * DD + n];
    uint32_t h0, l0, h1, l1;
    split2(w00, w01, h0, l0);
    split2(w10, w11, h1, l1);
    g_Wmma[(size_t)(l * NSTEP + s) * 128 + t] = make_uint4(h0, h1, l0, l1);
}

__global__ void relin_kernel(const float* __restrict__ rel_W,
                             const float* __restrict__ rel_b) {
    const int bx = blockIdx.x;
    const int l = bx / RR, r = bx - l * RR;
    const int t = threadIdx.x;
    const int d = t & 31, b = t >> 5;
    const float* W = rel_W + (size_t)l * DD * RR * DD + (size_t)r * DD + d;
    float acc = rel_b[(size_t)l * RR * DD + r * DD + d];
#pragma unroll
    for (int k = 0; k < DD; ++k)
        acc += g_query[b * DD + k] * W[(size_t)k * RR * DD];
    ((float*)g_relin)[((size_t)(l * RR + r) * DD + d) * 4 + b] = acc;
}

// ---------------- fused conv layer ----------------
__device__ __forceinline__ void edge_acc(const int4 ep, const float4 rv, const float4 hh,
                                         float4& sum, float4& sq, float4& mx, float4& mn) {
    const float w = __int_as_float(ep.z);
    float m, mw;
    m = rv.x * hh.x; mw = m * w; sum.x += mw; sq.x = fmaf(m, mw, sq.x); mx.x = fmaxf(mx.x, mw); mn.x = fminf(mn.x, mw);
    m = rv.y * hh.y; mw = m * w; sum.y += mw; sq.y = fmaf(m, mw, sq.y); mx.y = fmaxf(mx.y, mw); mn.y = fminf(mn.y, mw);
    m = rv.z * hh.z; mw = m * w; sum.z += mw; sq.z = fmaf(m, mw, sq.z); mx.z = fmaxf(mx.z, mw); mn.z = fminf(mn.z, mw);
    m = rv.w * hh.w; mw = m * w; sum.w += mw; sq.w = fmaf(m, mw, sq.w); mx.w = fmaxf(mx.w, mw); mn.w = fminf(mn.w, mw);
}

// write split pair into catH/catL for the 4 rows (b components) of this node
#define WRITE_PAIR(p, x0, x1)                                              \
    do {                                                                   \
        uint32_t hh_, ll_;                                                 \
        split2((x0).x, (x1).x, hh_, ll_);                                  \
        catH[p][r0] = hh_; catL[p][r0] = ll_;                              \
        split2((x0).y, (x1).y, hh_, ll_);                                  \
        catH[p][r0 + 1] = hh_; catL[p][r0 + 1] = ll_;                      \
        split2((x0).z, (x1).z, hh_, ll_);                                  \
        catH[p][r0 + 2] = hh_; catL[p][r0 + 2] = ll_;                      \
        split2((x0).w, (x1).w, hh_, ll_);                                  \
        catH[p][r0 + 3] = hh_; catL[p][r0 + 3] = ll_;                      \
    } while (0)

__global__ void __launch_bounds__(128) conv_kernel(
    const float* __restrict__ lin_b,
    const float4* __restrict__ hid_in, float4* __restrict__ hid_out,
    const int* __restrict__ h_index, int layer)
{
    __shared__ uint32_t catH[KD / 2][17];   // 14.1KB  [k-pair][row16]
    __shared__ uint32_t catL[KD / 2][17];   // 14.1KB
    __shared__ float sD[16][33];            // 2.1KB
    __shared__ int s_act[4];
    __shared__ float2 s_scl[4];

    const int t = threadIdx.x, w = t >> 5, lane = t & 31;
    const int v = blockIdx.x * 4 + w;
    const int d = lane;
    const float4* relin = g_relin + (size_t)layer * RR * DD;

    // ---- message phase (warp per node) ----
    {
        float4 m0 = g_bound[v * DD + d];
        float4 sum = m0, mx = m0, mn = m0;
        float4 sq = make_float4(m0.x * m0.x, m0.y * m0.y, m0.z * m0.z, m0.w * m0.w);
        const float4 hv = __ldg(&hid_in[v * DD + d]);
        int p = g_rowptr[v];
        const int e_ = g_rowptr[v + 1];
        const int degv = e_ - p;
        int act;

        if (layer == 0) {
            const int4 h = *(const int4*)h_index;
            act = (v == h.x) | (v == h.y) | (v == h.z) | (v == h.w);
            int nacc = 0;
            for (; p < e_; ++p) {
                const int4 ep = __ldg(&g_epack[p]);
                const int nin = ep.x;
                if (nin == h.x || nin == h.y || nin == h.z || nin == h.w) {
                    act = 1; ++nacc;
                    const float4 rv = __ldg(&relin[ep.y * DD + d]);
                    const float4 hh = __ldg(&hid_in[nin * DD + d]);
                    edge_acc(ep, rv, hh, sum, sq, mx, mn);
                }
            }
            if (nacc < degv) {
                mx.x = fmaxf(mx.x, 0.f); mx.y = fmaxf(mx.y, 0.f); mx.z = fmaxf(mx.z, 0.f); mx.w = fmaxf(mx.w, 0.f);
                mn.x = fminf(mn.x, 0.f); mn.y = fminf(mn.y, 0.f); mn.z = fminf(mn.z, 0.f); mn.w = fminf(mn.w, 0.f);
            }
        } else {
            act = 1;
            for (; p + 4 <= e_; p += 4) {
                const int4 e0 = __ldg(&g_epack[p + 0]);
                const int4 e1 = __ldg(&g_epack[p + 1]);
                const int4 e2 = __ldg(&g_epack[p + 2]);
                const int4 e3 = __ldg(&g_epack[p + 3]);
                const float4 rv0 = __ldg(&relin[e0.y * DD + d]);
                const float4 hh0 = __ldg(&hid_in[e0.x * DD + d]);
                const float4 rv1 = __ldg(&relin[e1.y * DD + d]);
                const float4 hh1 = __ldg(&hid_in[e1.x * DD + d]);
                const float4 rv2 = __ldg(&relin[e2.y * DD + d]);
                const float4 hh2 = __ldg(&hid_in[e2.x * DD + d]);
                const float4 rv3 = __ldg(&relin[e3.y * DD + d]);
                const float4 hh3 = __ldg(&hid_in[e3.x * DD + d]);
                edge_acc(e0, rv0, hh0, sum, sq, mx, mn);
                edge_acc(e1, rv1, hh1, sum, sq, mx, mn);
                edge_acc(e2, rv2, hh2, sum, sq, mx, mn);
                edge_acc(e3, rv3, hh3, sum, sq, mx, mn);
            }
            for (; p < e_; ++p) {
                const int4 e0 = __ldg(&g_epack[p]);
                const float4 rv0 = __ldg(&relin[e0.y * DD + d]);
                const float4 hh0 = __ldg(&hid_in[e0.x * DD + d]);
                edge_acc(e0, rv0, hh0, sum, sq, mx, mn);
            }
        }

        if (lane == 0) { s_act[w] = act; s_scl[w] = g_sc[v]; }

        if (act) {
            const float inv = 1.0f / (float)(degv + 1);
            float4 mean, var, sd;
            mean.x = sum.x * inv; mean.y = sum.y * inv; mean.z = sum.z * inv; mean.w = sum.w * inv;
            var.x = sq.x * inv - mean.x * mean.x; var.y = sq.y * inv - mean.y * mean.y;
            var.z = sq.z * inv - mean.z * mean.z; var.w = sq.w * inv - mean.w * mean.w;
            sd.x = sqrtf(fmaxf(var.x, EPSF)); sd.y = sqrtf(fmaxf(var.y, EPSF));
            sd.z = sqrtf(fmaxf(var.z, EPSF)); sd.w = sqrtf(fmaxf(var.w, EPSF));
            const float2 sc = g_sc[v];
            const int r0 = w * 4;

            // hidden pairs: even lanes write pair (d, d+1)
            float4 hv1;
            hv1.x = __shfl_down_sync(0xffffffffu, hv.x, 1);
            hv1.y = __shfl_down_sync(0xffffffffu, hv.y, 1);
            hv1.z = __shfl_down_sync(0xffffffffu, hv.z, 1);
            hv1.w = __shfl_down_sync(0xffffffffu, hv.w, 1);
            if ((d & 1) == 0) WRITE_PAIR(d >> 1, hv, hv1);

            // stat pairs: lane d owns features k in [32+12d, 32+12d+12)
            float4 f[12];
            const float4 st4[4] = {mean, mx, mn, sd};
#pragma unroll
            for (int si = 0; si < 4; ++si) {
                const float4 fv = st4[si];
                f[si * 3 + 0] = fv;
                f[si * 3 + 1] = make_float4(fv.x * sc.x, fv.y * sc.x, fv.z * sc.x, fv.w * sc.x);
                f[si * 3 + 2] = make_float4(fv.x * sc.y, fv.y * sc.y, fv.z * sc.y, fv.w * sc.y);
            }
            const int pb = 16 + 6 * d;
#pragma unroll
            for (int pi = 0; pi < 6; ++pi)
                WRITE_PAIR(pb + pi, f[2 * pi], f[2 * pi + 1]);
        }
    }
    __syncthreads();

    const int anyact = s_act[0] | s_act[1] | s_act[2] | s_act[3];

    // ---- GEMM via mma.sync bf16 3-split: C[16x32] = cat[16x416] @ W ----
    if (anyact) {
        const uint4* Wp = g_Wmma + (size_t)layer * NSTEP * 128 + (w * 32 + lane);
        const int c = lane & 3, g = lane >> 2;
        float d0 = 0.f, d1 = 0.f, d2 = 0.f, d3 = 0.f;
#pragma unroll
        for (int s = 0; s < NSTEP; ++s) {
            const uint4 wv = __ldg(&Wp[(size_t)s * 128]);
            const int pA = s * 8 + c, pB = s * 8 + 4 + c;
            const uint32_t ah0 = catH[pA][g], ah1 = catH[pA][g + 8];
            const uint32_t ah2 = catH[pB][g], ah3 = catH[pB][g + 8];
            const uint32_t al0 = catL[pA][g], al1 = catL[pA][g + 8];
            const uint32_t al2 = catL[pB][g], al3 = catL[pB][g + 8];
            mma16816(d0, d1, d2, d3, ah0, ah1, ah2, ah3, wv.x, wv.y);   // hi*hi
            mma16816(d0, d1, d2, d3, ah0, ah1, ah2, ah3, wv.z, wv.w);   // hi*lo
            mma16816(d0, d1, d2, d3, al0, al1, al2, al3, wv.x, wv.y);   // lo*hi
        }
        const int j0 = 8 * w + 2 * c;
        sD[g][j0] = d0;     sD[g][j0 + 1] = d1;
        sD[g + 8][j0] = d2; sD[g + 8][j0 + 1] = d3;
    }
    __syncthreads();

    // ---- epilogue: warp w finalizes node slot w ----
    {
        const float bias = lin_b[layer * DD + lane];
        float4 o;
        if (s_act[w]) {
            o = make_float4(fmaxf(sD[w * 4 + 0][lane] + bias, 0.0f),
                            fmaxf(sD[w * 4 + 1][lane] + bias, 0.0f),
                            fmaxf(sD[w * 4 + 2][lane] + bias, 0.0f),
                            fmaxf(sD[w * 4 + 3][lane] + bias, 0.0f));
        } else {
            // exact fast path: all messages + hidden + boundary exactly 0
            const float sd = sqrtf(EPSF);
            const float2 sc = s_scl[w];
            const float c = g_csum[lane] + sc.x * g_csum[DD + lane] + sc.y * g_csum[2 * DD + lane];
            const float val = fmaxf(bias + sd * c, 0.0f);
            o = make_float4(val, val, val, val);
        }
        hid_out[v * DD + lane] = o;
    }
}

// ---------------- final MLP scoring ----------------
__global__ void __launch_bounds__(256) mlp_kernel(
    const float4* __restrict__ hid,
    const float* __restrict__ W1, const float* __restrict__ b1,
    const float* __restrict__ W2, const float* __restrict__ b2,
    float* __restrict__ out)
{
    __shared__ float  W1s[64 * 64];
    __shared__ float  W2s[64];
    __shared__ float  b1s[64];
    __shared__ float4 f2[NPB * 64];   // [slot][k] -> 4 b's

    const int t = threadIdx.x;
    for (int i = t; i < 64 * 64; i += 256) W1s[i] = W1[i];
    if (t < 64) { W2s[t] = W2[t]; b1s[t] = b1[t]; }

    const int vbase = blockIdx.x * NPB;
    for (int i = t; i < NPB * 64; i += 256) {
        const int k = i & 63;
        const int s = i >> 6;
        const int v = vbase + s;
        float4 val = make_float4(0.f, 0.f, 0.f, 0.f);
        if (v < NN) val = (k < DD) ? __ldg(&hid[v * DD + k]) : g_qT[k - DD];
        f2[i] = val;
    }
    __syncthreads();

    const int s = t >> 5, lane = t & 31;
    const int v = vbase + s;
    if (v < NN) {
        ull a01 = dup2(b1s[lane]),      a23 = a01;
        ull b01 = dup2(b1s[lane + 32]), b23 = b01;
        const ulonglong2* up = (const ulonglong2*)&f2[s * 64];
#pragma unroll 8
        for (int k = 0; k < 64; ++k) {
            const ulonglong2 u = up[k];
            const ull wa = dup2(W1s[k * 64 + lane]);
            const ull wb = dup2(W1s[k * 64 + lane + 32]);
            a01 = fma2(u.x, wa, a01); a23 = fma2(u.y, wa, a23);
            b01 = fma2(u.x, wb, b01); b23 = fma2(u.y, wb, b23);
        }
        const float2 fa01 = unpk(a01), fa23 = unpk(a23);
        const float2 fb01 = unpk(b01), fb23 = unpk(b23);
        const float accA[4] = {fa01.x, fa01.y, fa23.x, fa23.y};
        const float accB[4] = {fb01.x, fb01.y, fb23.x, fb23.y};
        const float w2a = W2s[lane], w2b = W2s[lane + 32];
        const float bias2 = b2[0];
#pragma unroll
        for (int bb = 0; bb < 4; ++bb) {
            float p = fmaxf(accA[bb], 0.0f) * w2a + fmaxf(accB[bb], 0.0f) * w2b;
#pragma unroll
            for (int off = 16; off > 0; off >>= 1)
                p += __shfl_down_sync(0xffffffffu, p, off);
            if (lane == 0) out[bb * NN + v] = p + bias2;
        }
    }
}

// ---------------- launch ----------------
extern "C" void kernel_launch(void* const* d_in, const int* in_sizes, int n_in,
                              void* d_out, int out_size) {
    const int*   node_in     = (const int*)  d_in[0];
    const int*   node_out    = (const int*)  d_in[1];
    const int*   relation    = (const int*)  d_in[2];
    const float* edge_weight = (const float*)d_in[3];
    const int*   h_index     = (const int*)  d_in[4];
    const int*   r_index     = (const int*)  d_in[5];
    const float* query_embed = (const float*)d_in[6];
    const float* rel_W  = (const float*)d_in[7];
    const float* rel_b  = (const float*)d_in[8];
    const float* lin_W  = (const float*)d_in[9];
    const float* lin_b  = (const float*)d_in[10];
    const float* mlp_W1 = (const float*)d_in[11];
    const float* mlp_b1 = (const float*)d_in[12];
    const float* mlp_W2 = (const float*)d_in[13];
    const float* mlp_b2 = (const float*)d_in[14];
    float* out = (float*)d_out;

    float4 *hA, *hB, *hBound;
    cudaGetSymbolAddress((void**)&hA, g_hidA);
    cudaGetSymbolAddress((void**)&hB, g_hidB);
    cudaGetSymbolAddress((void**)&hBound, g_bound);

    zero_kernel<<<512, 256>>>();
    hist_kernel<<<(NE + 255) / 256, 256>>>(node_out, edge_weight);
    scanA_kernel<<<SCAN_B, 1024>>>();
    scanB_kernel<<<SCAN_B, 1024>>>();
    scatter_kernel<<<(NE + 255) / 256, 256>>>(node_in, node_out, relation, edge_weight);
    init_kernel<<<1, 160>>>(h_index, r_index, query_embed, lin_W);
    wsplit_kernel<<<NL * NSTEP, 128>>>(lin_W);
    relin_kernel<<<NL * RR, 128>>>(rel_W, rel_b);

    const float4* hin = hBound;
    float4* houts[4] = {hA, hB, hA, hB};
    for (int l = 0; l < NL; ++l) {
        conv_kernel<<<NN / 4, 128>>>(lin_b, hin, houts[l], h_index, l);
        hin = houts[l];
    }
    mlp_kernel<<<(NN + NPB - 1) / NPB, 256>>>(hin, mlp_W1, mlp_b1, mlp_W2, mlp_b2, out);
}